// round 15
// baseline (speedup 1.0000x reference)
#include <cuda_runtime.h>
#include <cuda_fp16.h>
#include <cstdint>

#define Nn 50000
#define Ee 600000
#define Gg 512
#define Hh 128
#define SCAN_BLKS ((Nn + 255) / 256)   // 196
#define PROJ_BLKS 235                   // ceil(470/2), 2 table rows per 256-thr block
#define E4BLK ((Ee / 4 + 255) / 256)    // 586
#define L1BLK ((Nn + 3) / 4)            // 12500
#define EPSf 1e-5f
#define Pp 136                          // smem pitch in halfs (conflict-free)
#define GBLK (148 * 6)                  // persistent gather blocks, single wave @6/SM
#define GWARPS (GBLK * 8)               // persistent gather warps

typedef unsigned long long u64;

// ---------------- device scratch (no allocations allowed) ----------------
// g_hwh holds (h @ W) * dinv[row] in fp16 (row = 256B). Row Nn is a reserved
// ALL-ZERO row (never written) used to pad gather chunks branch-free.
__device__ __align__(16) __half2 g_hwh[(size_t)(Nn + 1) * 64];
__device__ __align__(16) __half2 g_aggh[(size_t)Nn * 64];  // aggregated, fp16
__device__ __align__(16) float g_P[470 * Hh];              // projected embedding tables
__device__ __align__(16) float g_dinv[Nn];
__device__ __align__(16) float g_bnsum[3 * Hh];
__device__ __align__(16) float g_bnsq[3 * Hh];
__device__ __align__(16) float g_pooled[Gg * Hh];
__device__ __align__(16) float g_cnt[Gg];
__device__ int g_degcnt[Nn];
__device__ int g_cursor[Nn];
__device__ int g_base[Nn + 1];
__device__ int g_esrc[Ee];
__device__ int g_sflag[SCAN_BLKS];     // lookback flags: (aggregate<<1)|1

// NOTE: per-replay zeroing of scratch happens at the TAIL of the graph (k_fc).
// First execution relies on CUDA zero-initialization of __device__ globals.

// ---------------- warp scan helper ----------------
__device__ __forceinline__ int warp_incl_scan(int v, int lane) {
#pragma unroll
    for (int off = 1; off < 32; off <<= 1) {
        int y = __shfl_up_sync(0xFFFFFFFFu, v, off);
        if (lane >= off) v += y;
    }
    return v;
}

// ---------------- HMMA m16n8k16 fp16 -> fp32 ----------------
__device__ __forceinline__ void mma16816(float4& c, unsigned a0, unsigned a1,
                                         unsigned a2, unsigned a3,
                                         unsigned b0, unsigned b1) {
    asm volatile(
        "mma.sync.aligned.m16n8k16.row.col.f32.f16.f16.f32 "
        "{%0,%1,%2,%3}, {%4,%5,%6,%7}, {%8,%9}, {%0,%1,%2,%3};"
        : "+f"(c.x), "+f"(c.y), "+f"(c.z), "+f"(c.w)
        : "r"(a0), "r"(a1), "r"(a2), "r"(a3), "r"(b0), "r"(b1));
}

// ---------------- degree count + graph-size count (int4 vectorized) ----------------
__global__ void k_count(const int* __restrict__ ei, const int* __restrict__ batch) {
    int j = blockIdx.x * blockDim.x + threadIdx.x;
    if (j < Ee / 4) {
        int4 d = ((const int4*)(ei + Ee))[j];
        atomicAdd(&g_degcnt[d.x], 1);
        atomicAdd(&g_degcnt[d.y], 1);
        atomicAdd(&g_degcnt[d.z], 1);
        atomicAdd(&g_degcnt[d.w], 1);
    }
    if (j < Nn / 4) {
        int4 b = ((const int4*)batch)[j];
        atomicAdd(&g_cnt[b.x], 1.0f);
        atomicAdd(&g_cnt[b.y], 1.0f);
        atomicAdd(&g_cnt[b.z], 1.0f);
        atomicAdd(&g_cnt[b.w], 1.0f);
    }
}

// ---------------- fused: decoupled-lookback scan (blocks 0..195) + W1-projection
__global__ void __launch_bounds__(256) k_scan_proj(
    const float* __restrict__ emb0, const float* __restrict__ emb1,
    const float* __restrict__ emb2, const float* __restrict__ emb5,
    const float* __restrict__ W1) {
    int bid = blockIdx.x;
    int tid = threadIdx.x;

    if (bid >= SCAN_BLKS) {
        int idx = (bid - SCAN_BLKS) * 2 + (tid >> 7);
        if (idx >= 470) return;
        int c = tid & 127;
        const float* emb; int koff, v;
        if (idx < 96)       { emb = emb0; koff = 1;  v = idx; }
        else if (idx < 192) { emb = emb1; koff = 33; v = idx - 96; }
        else if (idx < 288) { emb = emb2; koff = 65; v = idx - 192; }
        else                { emb = emb5; koff = 97; v = idx - 288; }
        float acc = 0.0f;
#pragma unroll
        for (int j = 0; j < 32; j++)
            acc += emb[v * 32 + j] * W1[(koff + j) * Hh + c];
        g_P[(size_t)idx * Hh + c] = acc;
        return;
    }

    __shared__ int wsum[8];
    __shared__ int wred[8];
    int lane = tid & 31, wp = tid >> 5;
    int i = bid * 256 + tid;
    int v = (i < Nn) ? g_degcnt[i] : 0;
    int incl = warp_incl_scan(v, lane);
    if (lane == 31) wsum[wp] = incl;
    __syncthreads();
    int woff = 0, total = 0;
#pragma unroll
    for (int w = 0; w < 8; w++) {
        woff += (w < wp) ? wsum[w] : 0;
        total += wsum[w];
    }
    int excl = woff + incl - v;

    if (tid == 0) atomicExch(&g_sflag[bid], (total << 1) | 1);

    int mysum = 0;
    if (tid < bid) {
        int f;
        do { f = atomicAdd(&g_sflag[tid], 0); } while (!(f & 1));
        mysum = f >> 1;
    }
#pragma unroll
    for (int off = 16; off > 0; off >>= 1)
        mysum += __shfl_down_sync(0xFFFFFFFFu, mysum, off);
    if (lane == 0) wred[wp] = mysum;
    __syncthreads();
    int prefix = 0;
#pragma unroll
    for (int w = 0; w < 8; w++) prefix += wred[w];

    if (i < Nn) {
        g_base[i] = excl + prefix;
        g_dinv[i] = rsqrtf((float)g_degcnt[i] + 1.0f);
    }
    if (i == 0) g_base[Nn] = Ee;
}

// ---------------- fused: CSR edge placement + layer-1 hw production ----------------
__global__ void __launch_bounds__(256) k_place_layer1(
    const int* __restrict__ ei, const float* __restrict__ x,
    const float* __restrict__ W1) {
    int tid = threadIdx.x;
    if (blockIdx.x < E4BLK) {
        int j = blockIdx.x * 256 + tid;
        if (j >= Ee / 4) return;
        int4 s = ((const int4*)ei)[j];
        int4 d = ((const int4*)(ei + Ee))[j];
        g_esrc[g_base[d.x] + atomicAdd(&g_cursor[d.x], 1)] = s.x;
        g_esrc[g_base[d.y] + atomicAdd(&g_cursor[d.y], 1)] = s.y;
        g_esrc[g_base[d.z] + atomicAdd(&g_cursor[d.z], 1)] = s.z;
        g_esrc[g_base[d.w] + atomicAdd(&g_cursor[d.w], 1)] = s.w;
        return;
    }
    int node = (blockIdx.x - E4BLK) * 4 + (tid >> 6);
    if (node >= Nn) return;
    int c2 = tid & 63;
    int c0 = c2 * 2;
    const float* xr = x + (size_t)node * 5;
    float pos = xr[0];
    int i0 = (int)xr[1], i1 = (int)xr[2], i2 = (int)xr[3], i5 = (int)xr[4];
    const float* p0 = g_P + (size_t)i0 * Hh;
    const float* p1 = g_P + (size_t)(96 + i1) * Hh;
    const float* p2 = g_P + (size_t)(192 + i2) * Hh;
    const float* p5 = g_P + (size_t)(288 + i5) * Hh;
    float di = g_dinv[node];
    float va = (pos * W1[c0]     + p0[c0]     + p1[c0]     + p2[c0]     + p5[c0]) * di;
    float vb = (pos * W1[c0 + 1] + p0[c0 + 1] + p1[c0 + 1] + p2[c0 + 1] + p5[c0 + 1]) * di;
    g_hwh[(size_t)node * 64 + c2] = __floats2half2_rn(va, vb);
}

// ---------------- PERSISTENT pipelined aggregation + self-loop + bias + BN stats ----
// Depth-2 software pipeline over the warp's node list: while processing node
// n's rows, the warp stages node n+1's indices (double-buffered smem) and
// prefetches node n+2's CSR base -> the per-node index-load latency is hidden.
// Staged buffer covers deg<=32; rare larger degrees use a shuffle overflow path.
__global__ void __launch_bounds__(256, 6) k_gather(int layer, const float* __restrict__ bias) {
    __shared__ float s_sum[8][132];
    __shared__ float s_sq[8][132];
    __shared__ int s_idx[8][2][32];
    int tid = threadIdx.x;
    int wp = tid >> 5;
    int lane = tid & 31;
    int half = lane >> 4;          // 0/1: which row of each load pair
    int sl = lane & 15;            // 16B chunk within row
    int c0 = sl * 8 + half * 4;    // 4 channels owned by this lane

    const uint4* hw4 = (const uint4*)g_hwh;
    float4 bv = *(const float4*)(bias + c0);

    float bnS0 = 0.f, bnS1 = 0.f, bnS2 = 0.f, bnS3 = 0.f;
    float bnQ0 = 0.f, bnQ1 = 0.f, bnQ2 = 0.f, bnQ3 = 0.f;

    int gw0 = blockIdx.x * 8 + wp;
    int sA = 0, eA = 0;            // CSR range of current node n
    int sB = 0, eB = 0;            // CSR range of node n+1
    int buf = 0;
    if (gw0 < Nn) {
        sA = g_base[gw0]; eA = g_base[gw0 + 1];
        int limA = min(eA - sA, 32);
        s_idx[wp][0][lane] = (lane < limA) ? g_esrc[sA + lane] : Nn;
        int g1 = gw0 + GWARPS;
        if (g1 < Nn) { sB = g_base[g1]; eB = g_base[g1 + 1]; }
    }
    __syncwarp();

    for (int gw = gw0; gw < Nn; gw += GWARPS) {
        int nxt = gw + GWARPS;
        int deg = eA - sA;
        float di = g_dinv[gw];

        // prefetch CSR base of node n+2
        int s2 = 0, e2 = 0;
        int g2 = nxt + GWARPS;
        if (g2 < Nn) { s2 = g_base[g2]; e2 = g_base[g2 + 1]; }
        // stage indices of node n+1 (latency hidden under row processing below)
        if (nxt < Nn) {
            int limB = min(eB - sB, 32);
            s_idx[wp][buf ^ 1][lane] = (lane < limB) ? g_esrc[sB + lane] : Nn;
        }

        float acc8[8];
#pragma unroll
        for (int k = 0; k < 8; k++) acc8[k] = 0.f;

        // staged chunk: slots 0..min(deg,32), rounded to 16
        int degC = min(deg, 32);
        int slots = (degC + 15) & ~15;
        for (int j = 0; j < slots; j += 16) {
            uint4 r[8];
#pragma unroll
            for (int q = 0; q < 8; q++) {
                int row = s_idx[wp][buf][j + 2 * q + half];   // LDS broadcast
                r[q] = hw4[(size_t)row * 16 + sl];
            }
#pragma unroll
            for (int p = 0; p < 4; p++) {
                uint4 ra = r[2 * p], rb = r[2 * p + 1];
                __half2 h0 = __hadd2(*(__half2*)&ra.x, *(__half2*)&rb.x);
                __half2 h1 = __hadd2(*(__half2*)&ra.y, *(__half2*)&rb.y);
                __half2 h2 = __hadd2(*(__half2*)&ra.z, *(__half2*)&rb.z);
                __half2 h3 = __hadd2(*(__half2*)&ra.w, *(__half2*)&rb.w);
                float2 f0 = __half22float2(h0), f1 = __half22float2(h1);
                float2 f2 = __half22float2(h2), f3 = __half22float2(h3);
                acc8[0] += f0.x; acc8[1] += f0.y;
                acc8[2] += f1.x; acc8[3] += f1.y;
                acc8[4] += f2.x; acc8[5] += f2.y;
                acc8[6] += f3.x; acc8[7] += f3.y;
            }
        }
        // overflow path for deg > 32 (rare; shuffle-broadcast, any degree)
        for (int base2 = 32; base2 < deg; base2 += 32) {
            int rem = deg - base2; if (rem > 32) rem = 32;
            int idx = (lane < rem) ? g_esrc[sA + base2 + lane] : Nn;
            int slots2 = (rem + 15) & ~15;
            for (int j = 0; j < slots2; j += 16) {
                uint4 r[8];
#pragma unroll
                for (int q = 0; q < 8; q++) {
                    int row = __shfl_sync(0xFFFFFFFFu, idx, j + 2 * q + half);
                    r[q] = hw4[(size_t)row * 16 + sl];
                }
#pragma unroll
                for (int p = 0; p < 4; p++) {
                    uint4 ra = r[2 * p], rb = r[2 * p + 1];
                    __half2 h0 = __hadd2(*(__half2*)&ra.x, *(__half2*)&rb.x);
                    __half2 h1 = __hadd2(*(__half2*)&ra.y, *(__half2*)&rb.y);
                    __half2 h2 = __hadd2(*(__half2*)&ra.z, *(__half2*)&rb.z);
                    __half2 h3 = __hadd2(*(__half2*)&ra.w, *(__half2*)&rb.w);
                    float2 f0 = __half22float2(h0), f1 = __half22float2(h1);
                    float2 f2 = __half22float2(h2), f3 = __half22float2(h3);
                    acc8[0] += f0.x; acc8[1] += f0.y;
                    acc8[2] += f1.x; acc8[3] += f1.y;
                    acc8[4] += f2.x; acc8[5] += f2.y;
                    acc8[6] += f3.x; acc8[7] += f3.y;
                }
            }
        }
        // self row (scaled by dinv[gw] already); half 1 reads the zero row
        {
            int rowself = (half == 0) ? gw : Nn;
            uint4 rs = hw4[(size_t)rowself * 16 + sl];
            float2 f0 = __half22float2(*(__half2*)&rs.x);
            float2 f1 = __half22float2(*(__half2*)&rs.y);
            float2 f2 = __half22float2(*(__half2*)&rs.z);
            float2 f3 = __half22float2(*(__half2*)&rs.w);
            acc8[0] += f0.x; acc8[1] += f0.y;
            acc8[2] += f1.x; acc8[3] += f1.y;
            acc8[4] += f2.x; acc8[5] += f2.y;
            acc8[6] += f3.x; acc8[7] += f3.y;
        }
        // combine the two half-warps
#pragma unroll
        for (int k = 0; k < 8; k++)
            acc8[k] += __shfl_xor_sync(0xFFFFFFFFu, acc8[k], 16);

        float ox = acc8[half * 4 + 0] * di + bv.x;
        float oy = acc8[half * 4 + 1] * di + bv.y;
        float oz = acc8[half * 4 + 2] * di + bv.z;
        float ow = acc8[half * 4 + 3] * di + bv.w;
        // store agg as fp16 (uint2 = 4 channels)
        {
            __half2 o01 = __floats2half2_rn(ox, oy);
            __half2 o23 = __floats2half2_rn(oz, ow);
            uint2 u = make_uint2(*(unsigned*)&o01, *(unsigned*)&o23);
            *(uint2*)(g_aggh + (size_t)gw * 64 + (c0 >> 1)) = u;
        }

        bnS0 += ox; bnQ0 += ox * ox;
        bnS1 += oy; bnQ1 += oy * oy;
        bnS2 += oz; bnQ2 += oz * oz;
        bnS3 += ow; bnQ3 += ow * ow;

        // rotate pipeline
        sA = sB; eA = eB; sB = s2; eB = e2;
        buf ^= 1;
        __syncwarp();
    }

    // one flush per block: smem across warps, then 256 global atomics
    s_sum[wp][c0 + 0] = bnS0; s_sq[wp][c0 + 0] = bnQ0;
    s_sum[wp][c0 + 1] = bnS1; s_sq[wp][c0 + 1] = bnQ1;
    s_sum[wp][c0 + 2] = bnS2; s_sq[wp][c0 + 2] = bnQ2;
    s_sum[wp][c0 + 3] = bnS3; s_sq[wp][c0 + 3] = bnQ3;
    __syncthreads();
    if (tid < 128) {
        float s = 0.f, q = 0.f;
#pragma unroll
        for (int w = 0; w < 8; w++) { s += s_sum[w][tid]; q += s_sq[w][tid]; }
        atomicAdd(&g_bnsum[layer * Hh + tid], s);
        atomicAdd(&g_bnsq[layer * Hh + tid], q);
    }
}

// ---------------- tensor-core GEMM: relu(bn(A)) @ W -> hw (pre-scaled fp16) ----------------
#define GEMM_SMEM (2 * 128 * Pp * 2)
__global__ void __launch_bounds__(256)
k_gemm(int layer, const float* __restrict__ gamma, const float* __restrict__ beta,
       const float* __restrict__ W) {
    extern __shared__ __half smh[];
    __half* As = smh;                 // 128 x Pp
    __half* Wt = smh + 128 * Pp;      // 128 x Pp (transposed W: Wt[n][k])
    __shared__ float s_scale[128];
    __shared__ float s_shift[128];
    int tid = threadIdx.x;
    int row0 = blockIdx.x * 128;

    if (tid < 128) {
        float mean = g_bnsum[layer * Hh + tid] * (1.0f / Nn);
        float var = g_bnsq[layer * Hh + tid] * (1.0f / Nn) - mean * mean;
        float sc = gamma[tid] * rsqrtf(var + EPSf);
        s_scale[tid] = sc;
        s_shift[tid] = beta[tid] - mean * sc;
    }

    for (int t = tid; t < 128 * 32; t += 256) {
        int k = t >> 5, n0 = (t & 31) * 4;
        float4 wv = ((const float4*)W)[t];
        Wt[(n0 + 0) * Pp + k] = __float2half_rn(wv.x);
        Wt[(n0 + 1) * Pp + k] = __float2half_rn(wv.y);
        Wt[(n0 + 2) * Pp + k] = __float2half_rn(wv.z);
        Wt[(n0 + 3) * Pp + k] = __float2half_rn(wv.w);
    }
    __syncthreads();

    // A tile: read fp16 agg (4 ch per t), BN+ReLU in fp32, store fp16
    for (int t = tid; t < 128 * 32; t += 256) {
        int r = t >> 5, q = t & 31;
        int grow = row0 + r;
        float4 v = make_float4(0.f, 0.f, 0.f, 0.f);
        if (grow < Nn) {
            uint2 u2 = *(const uint2*)(g_aggh + (size_t)grow * 64 + q * 2);
            float2 a01 = __half22float2(*(__half2*)&u2.x);
            float2 a23 = __half22float2(*(__half2*)&u2.y);
            float4 sc = ((const float4*)s_scale)[q];
            float4 sh = ((const float4*)s_shift)[q];
            v.x = fmaxf(a01.x * sc.x + sh.x, 0.f);
            v.y = fmaxf(a01.y * sc.y + sh.y, 0.f);
            v.z = fmaxf(a23.x * sc.z + sh.z, 0.f);
            v.w = fmaxf(a23.y * sc.w + sh.w, 0.f);
        }
        __half2 h0 = __floats2half2_rn(v.x, v.y);
        __half2 h1 = __floats2half2_rn(v.z, v.w);
        uint2 u = make_uint2(*(unsigned*)&h0, *(unsigned*)&h1);
        *(uint2*)(As + r * Pp + q * 4) = u;
    }
    __syncthreads();

    int wp = tid >> 5;
    int lane = tid & 31;
    int g = lane >> 2;
    int tg = lane & 3;

    float4 c[16];
#pragma unroll
    for (int nt = 0; nt < 16; nt++) c[nt] = make_float4(0.f, 0.f, 0.f, 0.f);

    const __half* Abase = As + (wp * 16 + g) * Pp + 2 * tg;
#pragma unroll
    for (int kk = 0; kk < 8; kk++) {
        const __half* Ar = Abase + kk * 16;
        unsigned a0 = *(const unsigned*)(Ar);
        unsigned a1 = *(const unsigned*)(Ar + 8 * Pp);
        unsigned a2 = *(const unsigned*)(Ar + 8);
        unsigned a3 = *(const unsigned*)(Ar + 8 * Pp + 8);
        const __half* Bb = Wt + g * Pp + kk * 16 + 2 * tg;
#pragma unroll
        for (int nt = 0; nt < 16; nt++) {
            const __half* Br = Bb + nt * 8 * Pp;
            unsigned b0 = *(const unsigned*)(Br);
            unsigned b1 = *(const unsigned*)(Br + 8);
            mma16816(c[nt], a0, a1, a2, a3, b0, b1);
        }
    }

    int r_lo = row0 + wp * 16 + g;
    int r_hi = r_lo + 8;
    bool ok_lo = (r_lo < Nn), ok_hi = (r_hi < Nn);
    float d_lo = ok_lo ? g_dinv[r_lo] : 0.f;
    float d_hi = ok_hi ? g_dinv[r_hi] : 0.f;
    __half2* out_lo = g_hwh + (size_t)r_lo * 64 + tg;
    __half2* out_hi = g_hwh + (size_t)r_hi * 64 + tg;
#pragma unroll
    for (int nt = 0; nt < 16; nt++) {
        if (ok_lo) out_lo[nt * 4] = __floats2half2_rn(c[nt].x * d_lo, c[nt].y * d_lo);
        if (ok_hi) out_hi[nt * 4] = __floats2half2_rn(c[nt].z * d_hi, c[nt].w * d_hi);
    }
}

// ---------------- pooling: batch is sorted -> run-length accumulate ----------------
__global__ void k_pool(const int* __restrict__ batch,
                       const float* __restrict__ gamma, const float* __restrict__ beta) {
    __shared__ int sb[128];
    int c = threadIdx.x;
    int r0 = blockIdx.x * 128;
    int nrows = min(128, Nn - r0);
    if (c < nrows) sb[c] = batch[r0 + c];
    float mean = g_bnsum[2 * Hh + c] * (1.0f / Nn);
    float var = g_bnsq[2 * Hh + c] * (1.0f / Nn) - mean * mean;
    float sc = gamma[c] * rsqrtf(var + EPSf);
    float sh = beta[c] - mean * sc;
    __syncthreads();
    const __half* aggh = (const __half*)g_aggh;
    float acc = 0.f;
    int cur = sb[0];
    for (int r = 0; r < nrows; r++) {
        int gr = sb[r];
        if (gr != cur) { atomicAdd(&g_pooled[cur * Hh + c], acc); acc = 0.f; cur = gr; }
        float v = __half2float(aggh[(size_t)(r0 + r) * Hh + c]);
        acc += fmaxf(v * sc + sh, 0.f);
    }
    atomicAdd(&g_pooled[cur * Hh + c], acc);
}

// ---------------- final FC + TAIL ZEROING for next replay ----------------
__global__ void k_fc(const float* __restrict__ fcW, const float* __restrict__ fcb,
                     float* __restrict__ out) {
    int g = blockIdx.x, c = threadIdx.x;
    int t = g * 128 + c;
    float v = g_pooled[g * Hh + c] / fmaxf(g_cnt[g], 1.0f);
    g_pooled[g * Hh + c] = 0.0f;
    __shared__ float s0[128], s1[128], s2[128];
    s0[c] = v * fcW[c * 3 + 0];
    s1[c] = v * fcW[c * 3 + 1];
    s2[c] = v * fcW[c * 3 + 2];
    __syncthreads();
    for (int off = 64; off > 0; off >>= 1) {
        if (c < off) { s0[c] += s0[c + off]; s1[c] += s1[c + off]; s2[c] += s2[c + off]; }
        __syncthreads();
    }
    if (c == 0) {
        out[g * 3 + 0] = s0[0] + fcb[0];
        out[g * 3 + 1] = s1[0] + fcb[1];
        out[g * 3 + 2] = s2[0] + fcb[2];
        g_cnt[g] = 0.0f;
    }
    if (t < Nn) { g_degcnt[t] = 0; g_cursor[t] = 0; }
    if (t < SCAN_BLKS) g_sflag[t] = 0;
    if (t < 3 * Hh) { g_bnsum[t] = 0.0f; g_bnsq[t] = 0.0f; }
}

// ---------------- launch ----------------
extern "C" void kernel_launch(void* const* d_in, const int* in_sizes, int n_in,
                              void* d_out, int out_size) {
    const float* x     = (const float*)d_in[0];
    const int*   ei    = (const int*)  d_in[1];
    const int*   batch = (const int*)  d_in[2];
    const float* emb0  = (const float*)d_in[3];
    const float* emb1  = (const float*)d_in[4];
    const float* emb2  = (const float*)d_in[5];
    const float* emb5  = (const float*)d_in[6];
    const float* W1    = (const float*)d_in[7];
    const float* b1    = (const float*)d_in[8];
    const float* W2    = (const float*)d_in[9];
    const float* b2    = (const float*)d_in[10];
    const float* W3    = (const float*)d_in[11];
    const float* b3    = (const float*)d_in[12];
    const float* g1    = (const float*)d_in[13];
    const float* be1   = (const float*)d_in[14];
    const float* g2    = (const float*)d_in[15];
    const float* be2   = (const float*)d_in[16];
    const float* g3    = (const float*)d_in[17];
    const float* be3   = (const float*)d_in[18];
    const float* fcW   = (const float*)d_in[19];
    const float* fcb   = (const float*)d_in[20];
    float* out = (float*)d_out;

    cudaFuncSetAttribute(k_gemm, cudaFuncAttributeMaxDynamicSharedMemorySize, GEMM_SMEM);

    const int nblk = (Nn + 127) / 128;          // 391

    // 10-kernel critical path
    k_count<<<E4BLK, 256>>>(ei, batch);
    k_scan_proj<<<SCAN_BLKS + PROJ_BLKS, 256>>>(emb0, emb1, emb2, emb5, W1);
    k_place_layer1<<<E4BLK + L1BLK, 256>>>(ei, x, W1);

    k_gather<<<GBLK, 256>>>(0, b1);
    k_gemm<<<nblk, 256, GEMM_SMEM>>>(0, g1, be1, W2);
    k_gather<<<GBLK, 256>>>(1, b2);
    k_gemm<<<nblk, 256, GEMM_SMEM>>>(1, g2, be2, W3);
    k_gather<<<GBLK, 256>>>(2, b3);

    k_pool<<<nblk, 128>>>(batch, g3, be3);
    k_fc<<<Gg, 128>>>(fcW, fcb, out);
}

// round 16
// speedup vs baseline: 1.3709x; 1.3709x over previous
#include <cuda_runtime.h>
#include <cuda_fp16.h>
#include <cstdint>

#define Nn 50000
#define Ee 600000
#define Gg 512
#define Hh 128
#define SCAN_BLKS ((Nn + 255) / 256)   // 196
#define PROJ_BLKS 235                   // ceil(470/2), 2 table rows per 256-thr block
#define E4BLK ((Ee / 4 + 255) / 256)    // 586
#define L1BLK ((Nn + 3) / 4)            // 12500
#define EPSf 1e-5f
#define Pp 136                          // smem pitch in halfs (conflict-free)
#define GBLK (148 * 6)                  // persistent gather blocks, single wave @6/SM
#define GWARPS (GBLK * 8)               // persistent gather warps

typedef unsigned long long u64;

// ---------------- device scratch (no allocations allowed) ----------------
// g_hwh holds (h @ W) * dinv[row] in fp16 (row = 256B). Row Nn is a reserved
// ALL-ZERO row (never written) used to pad gather chunks branch-free.
__device__ __align__(16) __half2 g_hwh[(size_t)(Nn + 1) * 64];
__device__ __align__(16) float g_agg[(size_t)Nn * Hh];     // aggregated (GEMM/pool input)
__device__ __align__(16) float g_P[470 * Hh];              // projected embedding tables
__device__ __align__(16) float g_dinv[Nn];
__device__ __align__(16) float g_bnsum[3 * Hh];
__device__ __align__(16) float g_bnsq[3 * Hh];
__device__ __align__(16) float g_pooled[Gg * Hh];
__device__ __align__(16) float g_cnt[Gg];
__device__ int g_degcnt[Nn];
__device__ int g_cursor[Nn];
__device__ int g_base[Nn + 1];
__device__ int g_esrc[Ee];
__device__ int g_sflag[SCAN_BLKS];     // lookback flags: (aggregate<<1)|1

// NOTE: per-replay zeroing of scratch happens at the TAIL of the graph (k_fc).
// First execution relies on CUDA zero-initialization of __device__ globals.

// ---------------- warp scan helper ----------------
__device__ __forceinline__ int warp_incl_scan(int v, int lane) {
#pragma unroll
    for (int off = 1; off < 32; off <<= 1) {
        int y = __shfl_up_sync(0xFFFFFFFFu, v, off);
        if (lane >= off) v += y;
    }
    return v;
}

// ---------------- HMMA m16n8k16 fp16 -> fp32 ----------------
__device__ __forceinline__ void mma16816(float4& c, unsigned a0, unsigned a1,
                                         unsigned a2, unsigned a3,
                                         unsigned b0, unsigned b1) {
    asm volatile(
        "mma.sync.aligned.m16n8k16.row.col.f32.f16.f16.f32 "
        "{%0,%1,%2,%3}, {%4,%5,%6,%7}, {%8,%9}, {%0,%1,%2,%3};"
        : "+f"(c.x), "+f"(c.y), "+f"(c.z), "+f"(c.w)
        : "r"(a0), "r"(a1), "r"(a2), "r"(a3), "r"(b0), "r"(b1));
}

// ---------------- degree count + graph-size count (int4 vectorized) ----------------
__global__ void k_count(const int* __restrict__ ei, const int* __restrict__ batch) {
    int j = blockIdx.x * blockDim.x + threadIdx.x;
    if (j < Ee / 4) {
        int4 d = ((const int4*)(ei + Ee))[j];
        atomicAdd(&g_degcnt[d.x], 1);
        atomicAdd(&g_degcnt[d.y], 1);
        atomicAdd(&g_degcnt[d.z], 1);
        atomicAdd(&g_degcnt[d.w], 1);
    }
    if (j < Nn / 4) {
        int4 b = ((const int4*)batch)[j];
        atomicAdd(&g_cnt[b.x], 1.0f);
        atomicAdd(&g_cnt[b.y], 1.0f);
        atomicAdd(&g_cnt[b.z], 1.0f);
        atomicAdd(&g_cnt[b.w], 1.0f);
    }
}

// ---------------- fused: decoupled-lookback scan (blocks 0..195) + W1-projection
__global__ void __launch_bounds__(256) k_scan_proj(
    const float* __restrict__ emb0, const float* __restrict__ emb1,
    const float* __restrict__ emb2, const float* __restrict__ emb5,
    const float* __restrict__ W1) {
    int bid = blockIdx.x;
    int tid = threadIdx.x;

    if (bid >= SCAN_BLKS) {
        int idx = (bid - SCAN_BLKS) * 2 + (tid >> 7);
        if (idx >= 470) return;
        int c = tid & 127;
        const float* emb; int koff, v;
        if (idx < 96)       { emb = emb0; koff = 1;  v = idx; }
        else if (idx < 192) { emb = emb1; koff = 33; v = idx - 96; }
        else if (idx < 288) { emb = emb2; koff = 65; v = idx - 192; }
        else                { emb = emb5; koff = 97; v = idx - 288; }
        float acc = 0.0f;
#pragma unroll
        for (int j = 0; j < 32; j++)
            acc += emb[v * 32 + j] * W1[(koff + j) * Hh + c];
        g_P[(size_t)idx * Hh + c] = acc;
        return;
    }

    __shared__ int wsum[8];
    __shared__ int wred[8];
    int lane = tid & 31, wp = tid >> 5;
    int i = bid * 256 + tid;
    int v = (i < Nn) ? g_degcnt[i] : 0;
    int incl = warp_incl_scan(v, lane);
    if (lane == 31) wsum[wp] = incl;
    __syncthreads();
    int woff = 0, total = 0;
#pragma unroll
    for (int w = 0; w < 8; w++) {
        woff += (w < wp) ? wsum[w] : 0;
        total += wsum[w];
    }
    int excl = woff + incl - v;

    if (tid == 0) atomicExch(&g_sflag[bid], (total << 1) | 1);

    int mysum = 0;
    if (tid < bid) {
        int f;
        do { f = atomicAdd(&g_sflag[tid], 0); } while (!(f & 1));
        mysum = f >> 1;
    }
#pragma unroll
    for (int off = 16; off > 0; off >>= 1)
        mysum += __shfl_down_sync(0xFFFFFFFFu, mysum, off);
    if (lane == 0) wred[wp] = mysum;
    __syncthreads();
    int prefix = 0;
#pragma unroll
    for (int w = 0; w < 8; w++) prefix += wred[w];

    if (i < Nn) {
        g_base[i] = excl + prefix;
        g_dinv[i] = rsqrtf((float)g_degcnt[i] + 1.0f);
    }
    if (i == 0) g_base[Nn] = Ee;
}

// ---------------- fused: CSR edge placement + layer-1 hw production ----------------
__global__ void __launch_bounds__(256) k_place_layer1(
    const int* __restrict__ ei, const float* __restrict__ x,
    const float* __restrict__ W1) {
    int tid = threadIdx.x;
    if (blockIdx.x < E4BLK) {
        int j = blockIdx.x * 256 + tid;
        if (j >= Ee / 4) return;
        int4 s = ((const int4*)ei)[j];
        int4 d = ((const int4*)(ei + Ee))[j];
        g_esrc[g_base[d.x] + atomicAdd(&g_cursor[d.x], 1)] = s.x;
        g_esrc[g_base[d.y] + atomicAdd(&g_cursor[d.y], 1)] = s.y;
        g_esrc[g_base[d.z] + atomicAdd(&g_cursor[d.z], 1)] = s.z;
        g_esrc[g_base[d.w] + atomicAdd(&g_cursor[d.w], 1)] = s.w;
        return;
    }
    int node = (blockIdx.x - E4BLK) * 4 + (tid >> 6);
    if (node >= Nn) return;
    int c2 = tid & 63;
    int c0 = c2 * 2;
    const float* xr = x + (size_t)node * 5;
    float pos = xr[0];
    int i0 = (int)xr[1], i1 = (int)xr[2], i2 = (int)xr[3], i5 = (int)xr[4];
    const float* p0 = g_P + (size_t)i0 * Hh;
    const float* p1 = g_P + (size_t)(96 + i1) * Hh;
    const float* p2 = g_P + (size_t)(192 + i2) * Hh;
    const float* p5 = g_P + (size_t)(288 + i5) * Hh;
    float di = g_dinv[node];
    float va = (pos * W1[c0]     + p0[c0]     + p1[c0]     + p2[c0]     + p5[c0]) * di;
    float vb = (pos * W1[c0 + 1] + p0[c0 + 1] + p1[c0 + 1] + p2[c0 + 1] + p5[c0 + 1]) * di;
    g_hwh[(size_t)node * 64 + c2] = __floats2half2_rn(va, vb);
}

// ---------------- PERSISTENT fused aggregation + self-loop + bias + BN stats ------
// Single-wave persistent grid (6 blocks/SM enforced via launch_bounds), warp
// strides over ~7 nodes; BN partials in registers; ONE barrier per kernel.
__global__ void __launch_bounds__(256, 6) k_gather(int layer, const float* __restrict__ bias) {
    __shared__ float s_sum[8][132];
    __shared__ float s_sq[8][132];
    __shared__ int s_idx[8][96];
    int tid = threadIdx.x;
    int wp = tid >> 5;
    int lane = tid & 31;
    int half = lane >> 4;          // 0/1: which row of each load pair
    int sl = lane & 15;            // 16B chunk within row
    int c0 = sl * 8 + half * 4;    // 4 channels owned by this lane

    const uint4* hw4 = (const uint4*)g_hwh;
    float4 bv = *(const float4*)(bias + c0);

    float bnS0 = 0.f, bnS1 = 0.f, bnS2 = 0.f, bnS3 = 0.f;
    float bnQ0 = 0.f, bnQ1 = 0.f, bnQ2 = 0.f, bnQ3 = 0.f;

    for (int gw = blockIdx.x * 8 + wp; gw < Nn; gw += GWARPS) {
        int s = g_base[gw], e = g_base[gw + 1];
        int deg = e - s;
        float di = g_dinv[gw];
        float acc8[8];
#pragma unroll
        for (int k = 0; k < 8; k++) acc8[k] = 0.f;

        for (int base = 0; base < deg; base += 96) {
            int rem = deg - base; if (rem > 96) rem = 96;
            int slots = (rem + 15) & ~15;
            for (int j = lane; j < slots; j += 32)
                s_idx[wp][j] = (j < rem) ? g_esrc[s + base + j] : Nn;
            __syncwarp();
            for (int j = 0; j < slots; j += 16) {
                uint4 r[8];
#pragma unroll
                for (int q = 0; q < 8; q++) {
                    int row = s_idx[wp][j + 2 * q + half];   // LDS broadcast
                    r[q] = hw4[(size_t)row * 16 + sl];
                }
#pragma unroll
                for (int p = 0; p < 4; p++) {
                    uint4 ra = r[2 * p], rb = r[2 * p + 1];
                    __half2 h0 = __hadd2(*(__half2*)&ra.x, *(__half2*)&rb.x);
                    __half2 h1 = __hadd2(*(__half2*)&ra.y, *(__half2*)&rb.y);
                    __half2 h2 = __hadd2(*(__half2*)&ra.z, *(__half2*)&rb.z);
                    __half2 h3 = __hadd2(*(__half2*)&ra.w, *(__half2*)&rb.w);
                    float2 f0 = __half22float2(h0), f1 = __half22float2(h1);
                    float2 f2 = __half22float2(h2), f3 = __half22float2(h3);
                    acc8[0] += f0.x; acc8[1] += f0.y;
                    acc8[2] += f1.x; acc8[3] += f1.y;
                    acc8[4] += f2.x; acc8[5] += f2.y;
                    acc8[6] += f3.x; acc8[7] += f3.y;
                }
            }
            __syncwarp();   // staging buffer reuse safety
        }
        // self row (scaled by dinv[gw] already); half 1 reads the zero row
        {
            int rowself = (half == 0) ? gw : Nn;
            uint4 rs = hw4[(size_t)rowself * 16 + sl];
            float2 f0 = __half22float2(*(__half2*)&rs.x);
            float2 f1 = __half22float2(*(__half2*)&rs.y);
            float2 f2 = __half22float2(*(__half2*)&rs.z);
            float2 f3 = __half22float2(*(__half2*)&rs.w);
            acc8[0] += f0.x; acc8[1] += f0.y;
            acc8[2] += f1.x; acc8[3] += f1.y;
            acc8[4] += f2.x; acc8[5] += f2.y;
            acc8[6] += f3.x; acc8[7] += f3.y;
        }
        // combine the two half-warps
#pragma unroll
        for (int k = 0; k < 8; k++)
            acc8[k] += __shfl_xor_sync(0xFFFFFFFFu, acc8[k], 16);

        float ox = acc8[half * 4 + 0] * di + bv.x;
        float oy = acc8[half * 4 + 1] * di + bv.y;
        float oz = acc8[half * 4 + 2] * di + bv.z;
        float ow = acc8[half * 4 + 3] * di + bv.w;
        *(float4*)(g_agg + (size_t)gw * Hh + c0) = make_float4(ox, oy, oz, ow);

        bnS0 += ox; bnQ0 += ox * ox;
        bnS1 += oy; bnQ1 += oy * oy;
        bnS2 += oz; bnQ2 += oz * oz;
        bnS3 += ow; bnQ3 += ow * ow;
    }

    // one flush per block: smem across warps, then 256 global atomics
    s_sum[wp][c0 + 0] = bnS0; s_sq[wp][c0 + 0] = bnQ0;
    s_sum[wp][c0 + 1] = bnS1; s_sq[wp][c0 + 1] = bnQ1;
    s_sum[wp][c0 + 2] = bnS2; s_sq[wp][c0 + 2] = bnQ2;
    s_sum[wp][c0 + 3] = bnS3; s_sq[wp][c0 + 3] = bnQ3;
    __syncthreads();
    if (tid < 128) {
        float s = 0.f, q = 0.f;
#pragma unroll
        for (int w = 0; w < 8; w++) { s += s_sum[w][tid]; q += s_sq[w][tid]; }
        atomicAdd(&g_bnsum[layer * Hh + tid], s);
        atomicAdd(&g_bnsq[layer * Hh + tid], q);
    }
}

// ---------------- tensor-core GEMM: relu(bn(A)) @ W -> hw (pre-scaled fp16) ----------------
#define GEMM_SMEM (2 * 128 * Pp * 2)
__global__ void __launch_bounds__(256)
k_gemm(int layer, const float* __restrict__ gamma, const float* __restrict__ beta,
       const float* __restrict__ W) {
    extern __shared__ __half smh[];
    __half* As = smh;                 // 128 x Pp
    __half* Wt = smh + 128 * Pp;      // 128 x Pp (transposed W: Wt[n][k])
    __shared__ float s_scale[128];
    __shared__ float s_shift[128];
    int tid = threadIdx.x;
    int row0 = blockIdx.x * 128;

    if (tid < 128) {
        float mean = g_bnsum[layer * Hh + tid] * (1.0f / Nn);
        float var = g_bnsq[layer * Hh + tid] * (1.0f / Nn) - mean * mean;
        float sc = gamma[tid] * rsqrtf(var + EPSf);
        s_scale[tid] = sc;
        s_shift[tid] = beta[tid] - mean * sc;
    }

    for (int t = tid; t < 128 * 32; t += 256) {
        int k = t >> 5, n0 = (t & 31) * 4;
        float4 wv = ((const float4*)W)[t];
        Wt[(n0 + 0) * Pp + k] = __float2half_rn(wv.x);
        Wt[(n0 + 1) * Pp + k] = __float2half_rn(wv.y);
        Wt[(n0 + 2) * Pp + k] = __float2half_rn(wv.z);
        Wt[(n0 + 3) * Pp + k] = __float2half_rn(wv.w);
    }
    __syncthreads();

    for (int t = tid; t < 128 * 32; t += 256) {
        int r = t >> 5, q = t & 31;
        int grow = row0 + r;
        float4 v = make_float4(0.f, 0.f, 0.f, 0.f);
        if (grow < Nn) {
            v = ((const float4*)(g_agg + (size_t)grow * Hh))[q];
            float4 sc = ((const float4*)s_scale)[q];
            float4 sh = ((const float4*)s_shift)[q];
            v.x = fmaxf(v.x * sc.x + sh.x, 0.f);
            v.y = fmaxf(v.y * sc.y + sh.y, 0.f);
            v.z = fmaxf(v.z * sc.z + sh.z, 0.f);
            v.w = fmaxf(v.w * sc.w + sh.w, 0.f);
        }
        __half2 h0 = __floats2half2_rn(v.x, v.y);
        __half2 h1 = __floats2half2_rn(v.z, v.w);
        uint2 u = make_uint2(*(unsigned*)&h0, *(unsigned*)&h1);
        *(uint2*)(As + r * Pp + q * 4) = u;
    }
    __syncthreads();

    int wp = tid >> 5;
    int lane = tid & 31;
    int g = lane >> 2;
    int tg = lane & 3;

    float4 c[16];
#pragma unroll
    for (int nt = 0; nt < 16; nt++) c[nt] = make_float4(0.f, 0.f, 0.f, 0.f);

    const __half* Abase = As + (wp * 16 + g) * Pp + 2 * tg;
#pragma unroll
    for (int kk = 0; kk < 8; kk++) {
        const __half* Ar = Abase + kk * 16;
        unsigned a0 = *(const unsigned*)(Ar);
        unsigned a1 = *(const unsigned*)(Ar + 8 * Pp);
        unsigned a2 = *(const unsigned*)(Ar + 8);
        unsigned a3 = *(const unsigned*)(Ar + 8 * Pp + 8);
        const __half* Bb = Wt + g * Pp + kk * 16 + 2 * tg;
#pragma unroll
        for (int nt = 0; nt < 16; nt++) {
            const __half* Br = Bb + nt * 8 * Pp;
            unsigned b0 = *(const unsigned*)(Br);
            unsigned b1 = *(const unsigned*)(Br + 8);
            mma16816(c[nt], a0, a1, a2, a3, b0, b1);
        }
    }

    int r_lo = row0 + wp * 16 + g;
    int r_hi = r_lo + 8;
    bool ok_lo = (r_lo < Nn), ok_hi = (r_hi < Nn);
    float d_lo = ok_lo ? g_dinv[r_lo] : 0.f;
    float d_hi = ok_hi ? g_dinv[r_hi] : 0.f;
    __half2* out_lo = g_hwh + (size_t)r_lo * 64 + tg;
    __half2* out_hi = g_hwh + (size_t)r_hi * 64 + tg;
#pragma unroll
    for (int nt = 0; nt < 16; nt++) {
        if (ok_lo) out_lo[nt * 4] = __floats2half2_rn(c[nt].x * d_lo, c[nt].y * d_lo);
        if (ok_hi) out_hi[nt * 4] = __floats2half2_rn(c[nt].z * d_hi, c[nt].w * d_hi);
    }
}

// ---------------- pooling: batch is sorted -> run-length accumulate ----------------
// 256 threads: two half-block segments of 64 rows each -> serial chain halved;
// atomics merge across the segment boundary (and across blocks) as before.
__global__ void __launch_bounds__(256) k_pool(const int* __restrict__ batch,
                       const float* __restrict__ gamma, const float* __restrict__ beta) {
    __shared__ int sb[128];
    int tid = threadIdx.x;
    int c = tid & 127;
    int seg = tid >> 7;              // 0 or 1
    int r0 = blockIdx.x * 128;
    int nrows = min(128, Nn - r0);
    if (tid < nrows) sb[tid] = batch[r0 + tid];
    float mean = g_bnsum[2 * Hh + c] * (1.0f / Nn);
    float var = g_bnsq[2 * Hh + c] * (1.0f / Nn) - mean * mean;
    float sc = gamma[c] * rsqrtf(var + EPSf);
    float sh = beta[c] - mean * sc;
    __syncthreads();
    int rbeg = seg * 64;
    int rend = min(nrows, rbeg + 64);
    if (rbeg >= rend) return;
    float acc = 0.f;
    int cur = sb[rbeg];
    for (int r = rbeg; r < rend; r++) {
        int gr = sb[r];
        if (gr != cur) { atomicAdd(&g_pooled[cur * Hh + c], acc); acc = 0.f; cur = gr; }
        float v = g_agg[(size_t)(r0 + r) * Hh + c];
        acc += fmaxf(v * sc + sh, 0.f);
    }
    atomicAdd(&g_pooled[cur * Hh + c], acc);
}

// ---------------- final FC + TAIL ZEROING for next replay ----------------
__global__ void k_fc(const float* __restrict__ fcW, const float* __restrict__ fcb,
                     float* __restrict__ out) {
    int g = blockIdx.x, c = threadIdx.x;
    int t = g * 128 + c;
    float v = g_pooled[g * Hh + c] / fmaxf(g_cnt[g], 1.0f);
    g_pooled[g * Hh + c] = 0.0f;
    __shared__ float s0[128], s1[128], s2[128];
    s0[c] = v * fcW[c * 3 + 0];
    s1[c] = v * fcW[c * 3 + 1];
    s2[c] = v * fcW[c * 3 + 2];
    __syncthreads();
    for (int off = 64; off > 0; off >>= 1) {
        if (c < off) { s0[c] += s0[c + off]; s1[c] += s1[c + off]; s2[c] += s2[c + off]; }
        __syncthreads();
    }
    if (c == 0) {
        out[g * 3 + 0] = s0[0] + fcb[0];
        out[g * 3 + 1] = s1[0] + fcb[1];
        out[g * 3 + 2] = s2[0] + fcb[2];
        g_cnt[g] = 0.0f;
    }
    if (t < Nn) { g_degcnt[t] = 0; g_cursor[t] = 0; }
    if (t < SCAN_BLKS) g_sflag[t] = 0;
    if (t < 3 * Hh) { g_bnsum[t] = 0.0f; g_bnsq[t] = 0.0f; }
}

// ---------------- launch ----------------
extern "C" void kernel_launch(void* const* d_in, const int* in_sizes, int n_in,
                              void* d_out, int out_size) {
    const float* x     = (const float*)d_in[0];
    const int*   ei    = (const int*)  d_in[1];
    const int*   batch = (const int*)  d_in[2];
    const float* emb0  = (const float*)d_in[3];
    const float* emb1  = (const float*)d_in[4];
    const float* emb2  = (const float*)d_in[5];
    const float* emb5  = (const float*)d_in[6];
    const float* W1    = (const float*)d_in[7];
    const float* b1    = (const float*)d_in[8];
    const float* W2    = (const float*)d_in[9];
    const float* b2    = (const float*)d_in[10];
    const float* W3    = (const float*)d_in[11];
    const float* b3    = (const float*)d_in[12];
    const float* g1    = (const float*)d_in[13];
    const float* be1   = (const float*)d_in[14];
    const float* g2    = (const float*)d_in[15];
    const float* be2   = (const float*)d_in[16];
    const float* g3    = (const float*)d_in[17];
    const float* be3   = (const float*)d_in[18];
    const float* fcW   = (const float*)d_in[19];
    const float* fcb   = (const float*)d_in[20];
    float* out = (float*)d_out;

    cudaFuncSetAttribute(k_gemm, cudaFuncAttributeMaxDynamicSharedMemorySize, GEMM_SMEM);

    const int nblk = (Nn + 127) / 128;          // 391

    // 10-kernel critical path
    k_count<<<E4BLK, 256>>>(ei, batch);
    k_scan_proj<<<SCAN_BLKS + PROJ_BLKS, 256>>>(emb0, emb1, emb2, emb5, W1);
    k_place_layer1<<<E4BLK + L1BLK, 256>>>(ei, x, W1);

    k_gather<<<GBLK, 256>>>(0, b1);
    k_gemm<<<nblk, 256, GEMM_SMEM>>>(0, g1, be1, W2);
    k_gather<<<GBLK, 256>>>(1, b2);
    k_gemm<<<nblk, 256, GEMM_SMEM>>>(1, g2, be2, W3);
    k_gather<<<GBLK, 256>>>(2, b3);

    k_pool<<<nblk, 256>>>(batch, g3, be3);
    k_fc<<<Gg, 128>>>(fcW, fcb, out);
}

// round 17
// speedup vs baseline: 1.3927x; 1.0159x over previous
#include <cuda_runtime.h>
#include <cuda_fp16.h>
#include <cstdint>

#define Nn 50000
#define Ee 600000
#define Gg 512
#define Hh 128
#define SCAN_BLKS ((Nn + 255) / 256)   // 196
#define PROJ_BLKS 235                   // ceil(470/2), 2 table rows per 256-thr block
#define E4BLK ((Ee / 4 + 255) / 256)    // 586
#define L1BLK ((Nn + 3) / 4)            // 12500
#define EPSf 1e-5f
#define Pp 136                          // smem pitch in halfs (conflict-free)
#define GBLK (148 * 6)                  // persistent gather blocks, single wave @6/SM
#define GWARPS (GBLK * 8)               // persistent gather warps

typedef unsigned long long u64;

// ---------------- device scratch (no allocations allowed) ----------------
// g_hwh holds (h @ W) * dinv[row] in fp16 (row = 256B). Row Nn is a reserved
// ALL-ZERO row (never written) used to pad gather chunks branch-free.
__device__ __align__(16) __half2 g_hwh[(size_t)(Nn + 1) * 64];
__device__ __align__(16) __half2 g_aggh[(size_t)Nn * 64];  // aggregated, fp16
__device__ __align__(16) float g_P[470 * Hh];              // projected embedding tables
__device__ __align__(16) float g_dinv[Nn];
__device__ __align__(16) float g_bnsum[3 * Hh];
__device__ __align__(16) float g_bnsq[3 * Hh];
__device__ __align__(16) float g_pooled[Gg * Hh];
__device__ __align__(16) float g_cnt[Gg];
__device__ int g_degcnt[Nn];
__device__ int g_cursor[Nn];
__device__ int g_base[Nn + 1];
__device__ int g_esrc[Ee];
__device__ int g_sflag[SCAN_BLKS];     // lookback flags: (aggregate<<1)|1

// NOTE: per-replay zeroing of scratch happens at the TAIL of the graph (k_fc).
// First execution relies on CUDA zero-initialization of __device__ globals.

// ---------------- warp scan helper ----------------
__device__ __forceinline__ int warp_incl_scan(int v, int lane) {
#pragma unroll
    for (int off = 1; off < 32; off <<= 1) {
        int y = __shfl_up_sync(0xFFFFFFFFu, v, off);
        if (lane >= off) v += y;
    }
    return v;
}

// ---------------- HMMA m16n8k16 fp16 -> fp32 ----------------
__device__ __forceinline__ void mma16816(float4& c, unsigned a0, unsigned a1,
                                         unsigned a2, unsigned a3,
                                         unsigned b0, unsigned b1) {
    asm volatile(
        "mma.sync.aligned.m16n8k16.row.col.f32.f16.f16.f32 "
        "{%0,%1,%2,%3}, {%4,%5,%6,%7}, {%8,%9}, {%0,%1,%2,%3};"
        : "+f"(c.x), "+f"(c.y), "+f"(c.z), "+f"(c.w)
        : "r"(a0), "r"(a1), "r"(a2), "r"(a3), "r"(b0), "r"(b1));
}

// ---------------- degree count + graph-size count (int4 vectorized) ----------------
__global__ void k_count(const int* __restrict__ ei, const int* __restrict__ batch) {
    int j = blockIdx.x * blockDim.x + threadIdx.x;
    if (j < Ee / 4) {
        int4 d = ((const int4*)(ei + Ee))[j];
        atomicAdd(&g_degcnt[d.x], 1);
        atomicAdd(&g_degcnt[d.y], 1);
        atomicAdd(&g_degcnt[d.z], 1);
        atomicAdd(&g_degcnt[d.w], 1);
    }
    if (j < Nn / 4) {
        int4 b = ((const int4*)batch)[j];
        atomicAdd(&g_cnt[b.x], 1.0f);
        atomicAdd(&g_cnt[b.y], 1.0f);
        atomicAdd(&g_cnt[b.z], 1.0f);
        atomicAdd(&g_cnt[b.w], 1.0f);
    }
}

// ---------------- fused: decoupled-lookback scan (blocks 0..195) + W1-projection
__global__ void __launch_bounds__(256) k_scan_proj(
    const float* __restrict__ emb0, const float* __restrict__ emb1,
    const float* __restrict__ emb2, const float* __restrict__ emb5,
    const float* __restrict__ W1) {
    int bid = blockIdx.x;
    int tid = threadIdx.x;

    if (bid >= SCAN_BLKS) {
        int idx = (bid - SCAN_BLKS) * 2 + (tid >> 7);
        if (idx >= 470) return;
        int c = tid & 127;
        const float* emb; int koff, v;
        if (idx < 96)       { emb = emb0; koff = 1;  v = idx; }
        else if (idx < 192) { emb = emb1; koff = 33; v = idx - 96; }
        else if (idx < 288) { emb = emb2; koff = 65; v = idx - 192; }
        else                { emb = emb5; koff = 97; v = idx - 288; }
        float acc = 0.0f;
#pragma unroll
        for (int j = 0; j < 32; j++)
            acc += emb[v * 32 + j] * W1[(koff + j) * Hh + c];
        g_P[(size_t)idx * Hh + c] = acc;
        return;
    }

    __shared__ int wsum[8];
    __shared__ int wred[8];
    int lane = tid & 31, wp = tid >> 5;
    int i = bid * 256 + tid;
    int v = (i < Nn) ? g_degcnt[i] : 0;
    int incl = warp_incl_scan(v, lane);
    if (lane == 31) wsum[wp] = incl;
    __syncthreads();
    int woff = 0, total = 0;
#pragma unroll
    for (int w = 0; w < 8; w++) {
        woff += (w < wp) ? wsum[w] : 0;
        total += wsum[w];
    }
    int excl = woff + incl - v;

    if (tid == 0) atomicExch(&g_sflag[bid], (total << 1) | 1);

    int mysum = 0;
    if (tid < bid) {
        int f;
        do { f = atomicAdd(&g_sflag[tid], 0); } while (!(f & 1));
        mysum = f >> 1;
    }
#pragma unroll
    for (int off = 16; off > 0; off >>= 1)
        mysum += __shfl_down_sync(0xFFFFFFFFu, mysum, off);
    if (lane == 0) wred[wp] = mysum;
    __syncthreads();
    int prefix = 0;
#pragma unroll
    for (int w = 0; w < 8; w++) prefix += wred[w];

    if (i < Nn) {
        g_base[i] = excl + prefix;
        g_dinv[i] = rsqrtf((float)g_degcnt[i] + 1.0f);
    }
    if (i == 0) g_base[Nn] = Ee;
}

// ---------------- fused: CSR edge placement + layer-1 hw production ----------------
__global__ void __launch_bounds__(256) k_place_layer1(
    const int* __restrict__ ei, const float* __restrict__ x,
    const float* __restrict__ W1) {
    int tid = threadIdx.x;
    if (blockIdx.x < E4BLK) {
        int j = blockIdx.x * 256 + tid;
        if (j >= Ee / 4) return;
        int4 s = ((const int4*)ei)[j];
        int4 d = ((const int4*)(ei + Ee))[j];
        g_esrc[g_base[d.x] + atomicAdd(&g_cursor[d.x], 1)] = s.x;
        g_esrc[g_base[d.y] + atomicAdd(&g_cursor[d.y], 1)] = s.y;
        g_esrc[g_base[d.z] + atomicAdd(&g_cursor[d.z], 1)] = s.z;
        g_esrc[g_base[d.w] + atomicAdd(&g_cursor[d.w], 1)] = s.w;
        return;
    }
    int node = (blockIdx.x - E4BLK) * 4 + (tid >> 6);
    if (node >= Nn) return;
    int c2 = tid & 63;
    int c0 = c2 * 2;
    const float* xr = x + (size_t)node * 5;
    float pos = xr[0];
    int i0 = (int)xr[1], i1 = (int)xr[2], i2 = (int)xr[3], i5 = (int)xr[4];
    const float* p0 = g_P + (size_t)i0 * Hh;
    const float* p1 = g_P + (size_t)(96 + i1) * Hh;
    const float* p2 = g_P + (size_t)(192 + i2) * Hh;
    const float* p5 = g_P + (size_t)(288 + i5) * Hh;
    float di = g_dinv[node];
    float va = (pos * W1[c0]     + p0[c0]     + p1[c0]     + p2[c0]     + p5[c0]) * di;
    float vb = (pos * W1[c0 + 1] + p0[c0 + 1] + p1[c0 + 1] + p2[c0 + 1] + p5[c0 + 1]) * di;
    g_hwh[(size_t)node * 64 + c2] = __floats2half2_rn(va, vb);
}

// ---------------- PERSISTENT fused aggregation + self-loop + bias + BN stats ------
// Single-wave persistent grid (6 blocks/SM enforced via launch_bounds), warp
// strides over ~7 nodes; BN partials in registers; ONE barrier per kernel.
__global__ void __launch_bounds__(256, 6) k_gather(int layer, const float* __restrict__ bias) {
    __shared__ float s_sum[8][132];
    __shared__ float s_sq[8][132];
    __shared__ int s_idx[8][96];
    int tid = threadIdx.x;
    int wp = tid >> 5;
    int lane = tid & 31;
    int half = lane >> 4;          // 0/1: which row of each load pair
    int sl = lane & 15;            // 16B chunk within row
    int c0 = sl * 8 + half * 4;    // 4 channels owned by this lane

    const uint4* hw4 = (const uint4*)g_hwh;
    float4 bv = *(const float4*)(bias + c0);

    float bnS0 = 0.f, bnS1 = 0.f, bnS2 = 0.f, bnS3 = 0.f;
    float bnQ0 = 0.f, bnQ1 = 0.f, bnQ2 = 0.f, bnQ3 = 0.f;

    for (int gw = blockIdx.x * 8 + wp; gw < Nn; gw += GWARPS) {
        int s = g_base[gw], e = g_base[gw + 1];
        int deg = e - s;
        float di = g_dinv[gw];
        float acc8[8];
#pragma unroll
        for (int k = 0; k < 8; k++) acc8[k] = 0.f;

        for (int base = 0; base < deg; base += 96) {
            int rem = deg - base; if (rem > 96) rem = 96;
            int slots = (rem + 15) & ~15;
            for (int j = lane; j < slots; j += 32)
                s_idx[wp][j] = (j < rem) ? g_esrc[s + base + j] : Nn;
            __syncwarp();
            for (int j = 0; j < slots; j += 16) {
                uint4 r[8];
#pragma unroll
                for (int q = 0; q < 8; q++) {
                    int row = s_idx[wp][j + 2 * q + half];   // LDS broadcast
                    r[q] = hw4[(size_t)row * 16 + sl];
                }
#pragma unroll
                for (int p = 0; p < 4; p++) {
                    uint4 ra = r[2 * p], rb = r[2 * p + 1];
                    __half2 h0 = __hadd2(*(__half2*)&ra.x, *(__half2*)&rb.x);
                    __half2 h1 = __hadd2(*(__half2*)&ra.y, *(__half2*)&rb.y);
                    __half2 h2 = __hadd2(*(__half2*)&ra.z, *(__half2*)&rb.z);
                    __half2 h3 = __hadd2(*(__half2*)&ra.w, *(__half2*)&rb.w);
                    float2 f0 = __half22float2(h0), f1 = __half22float2(h1);
                    float2 f2 = __half22float2(h2), f3 = __half22float2(h3);
                    acc8[0] += f0.x; acc8[1] += f0.y;
                    acc8[2] += f1.x; acc8[3] += f1.y;
                    acc8[4] += f2.x; acc8[5] += f2.y;
                    acc8[6] += f3.x; acc8[7] += f3.y;
                }
            }
            __syncwarp();   // staging buffer reuse safety
        }
        // self row (scaled by dinv[gw] already); half 1 reads the zero row
        {
            int rowself = (half == 0) ? gw : Nn;
            uint4 rs = hw4[(size_t)rowself * 16 + sl];
            float2 f0 = __half22float2(*(__half2*)&rs.x);
            float2 f1 = __half22float2(*(__half2*)&rs.y);
            float2 f2 = __half22float2(*(__half2*)&rs.z);
            float2 f3 = __half22float2(*(__half2*)&rs.w);
            acc8[0] += f0.x; acc8[1] += f0.y;
            acc8[2] += f1.x; acc8[3] += f1.y;
            acc8[4] += f2.x; acc8[5] += f2.y;
            acc8[6] += f3.x; acc8[7] += f3.y;
        }
        // combine the two half-warps
#pragma unroll
        for (int k = 0; k < 8; k++)
            acc8[k] += __shfl_xor_sync(0xFFFFFFFFu, acc8[k], 16);

        float ox = acc8[half * 4 + 0] * di + bv.x;
        float oy = acc8[half * 4 + 1] * di + bv.y;
        float oz = acc8[half * 4 + 2] * di + bv.z;
        float ow = acc8[half * 4 + 3] * di + bv.w;
        // store agg as fp16 (uint2 = 4 channels, coalesced 256B per row)
        {
            __half2 o01 = __floats2half2_rn(ox, oy);
            __half2 o23 = __floats2half2_rn(oz, ow);
            uint2 u = make_uint2(*(unsigned*)&o01, *(unsigned*)&o23);
            *(uint2*)(g_aggh + (size_t)gw * 64 + (c0 >> 1)) = u;
        }

        bnS0 += ox; bnQ0 += ox * ox;
        bnS1 += oy; bnQ1 += oy * oy;
        bnS2 += oz; bnQ2 += oz * oz;
        bnS3 += ow; bnQ3 += ow * ow;
    }

    // one flush per block: smem across warps, then 256 global atomics
    s_sum[wp][c0 + 0] = bnS0; s_sq[wp][c0 + 0] = bnQ0;
    s_sum[wp][c0 + 1] = bnS1; s_sq[wp][c0 + 1] = bnQ1;
    s_sum[wp][c0 + 2] = bnS2; s_sq[wp][c0 + 2] = bnQ2;
    s_sum[wp][c0 + 3] = bnS3; s_sq[wp][c0 + 3] = bnQ3;
    __syncthreads();
    if (tid < 128) {
        float s = 0.f, q = 0.f;
#pragma unroll
        for (int w = 0; w < 8; w++) { s += s_sum[w][tid]; q += s_sq[w][tid]; }
        atomicAdd(&g_bnsum[layer * Hh + tid], s);
        atomicAdd(&g_bnsq[layer * Hh + tid], q);
    }
}

// ---------------- tensor-core GEMM: relu(bn(A)) @ W -> hw (pre-scaled fp16) ----------------
#define GEMM_SMEM (2 * 128 * Pp * 2)
__global__ void __launch_bounds__(256)
k_gemm(int layer, const float* __restrict__ gamma, const float* __restrict__ beta,
       const float* __restrict__ W) {
    extern __shared__ __half smh[];
    __half* As = smh;                 // 128 x Pp
    __half* Wt = smh + 128 * Pp;      // 128 x Pp (transposed W: Wt[n][k])
    __shared__ float s_scale[128];
    __shared__ float s_shift[128];
    int tid = threadIdx.x;
    int row0 = blockIdx.x * 128;

    if (tid < 128) {
        float mean = g_bnsum[layer * Hh + tid] * (1.0f / Nn);
        float var = g_bnsq[layer * Hh + tid] * (1.0f / Nn) - mean * mean;
        float sc = gamma[tid] * rsqrtf(var + EPSf);
        s_scale[tid] = sc;
        s_shift[tid] = beta[tid] - mean * sc;
    }

    for (int t = tid; t < 128 * 32; t += 256) {
        int k = t >> 5, n0 = (t & 31) * 4;
        float4 wv = ((const float4*)W)[t];
        Wt[(n0 + 0) * Pp + k] = __float2half_rn(wv.x);
        Wt[(n0 + 1) * Pp + k] = __float2half_rn(wv.y);
        Wt[(n0 + 2) * Pp + k] = __float2half_rn(wv.z);
        Wt[(n0 + 3) * Pp + k] = __float2half_rn(wv.w);
    }
    __syncthreads();

    // A tile: read fp16 agg (4 ch per t), BN+ReLU in fp32, store fp16
    for (int t = tid; t < 128 * 32; t += 256) {
        int r = t >> 5, q = t & 31;
        int grow = row0 + r;
        float4 v = make_float4(0.f, 0.f, 0.f, 0.f);
        if (grow < Nn) {
            uint2 u2 = *(const uint2*)(g_aggh + (size_t)grow * 64 + q * 2);
            float2 a01 = __half22float2(*(__half2*)&u2.x);
            float2 a23 = __half22float2(*(__half2*)&u2.y);
            float4 sc = ((const float4*)s_scale)[q];
            float4 sh = ((const float4*)s_shift)[q];
            v.x = fmaxf(a01.x * sc.x + sh.x, 0.f);
            v.y = fmaxf(a01.y * sc.y + sh.y, 0.f);
            v.z = fmaxf(a23.x * sc.z + sh.z, 0.f);
            v.w = fmaxf(a23.y * sc.w + sh.w, 0.f);
        }
        __half2 h0 = __floats2half2_rn(v.x, v.y);
        __half2 h1 = __floats2half2_rn(v.z, v.w);
        uint2 u = make_uint2(*(unsigned*)&h0, *(unsigned*)&h1);
        *(uint2*)(As + r * Pp + q * 4) = u;
    }
    __syncthreads();

    int wp = tid >> 5;
    int lane = tid & 31;
    int g = lane >> 2;
    int tg = lane & 3;

    float4 c[16];
#pragma unroll
    for (int nt = 0; nt < 16; nt++) c[nt] = make_float4(0.f, 0.f, 0.f, 0.f);

    const __half* Abase = As + (wp * 16 + g) * Pp + 2 * tg;
#pragma unroll
    for (int kk = 0; kk < 8; kk++) {
        const __half* Ar = Abase + kk * 16;
        unsigned a0 = *(const unsigned*)(Ar);
        unsigned a1 = *(const unsigned*)(Ar + 8 * Pp);
        unsigned a2 = *(const unsigned*)(Ar + 8);
        unsigned a3 = *(const unsigned*)(Ar + 8 * Pp + 8);
        const __half* Bb = Wt + g * Pp + kk * 16 + 2 * tg;
#pragma unroll
        for (int nt = 0; nt < 16; nt++) {
            const __half* Br = Bb + nt * 8 * Pp;
            unsigned b0 = *(const unsigned*)(Br);
            unsigned b1 = *(const unsigned*)(Br + 8);
            mma16816(c[nt], a0, a1, a2, a3, b0, b1);
        }
    }

    int r_lo = row0 + wp * 16 + g;
    int r_hi = r_lo + 8;
    bool ok_lo = (r_lo < Nn), ok_hi = (r_hi < Nn);
    float d_lo = ok_lo ? g_dinv[r_lo] : 0.f;
    float d_hi = ok_hi ? g_dinv[r_hi] : 0.f;
    __half2* out_lo = g_hwh + (size_t)r_lo * 64 + tg;
    __half2* out_hi = g_hwh + (size_t)r_hi * 64 + tg;
#pragma unroll
    for (int nt = 0; nt < 16; nt++) {
        if (ok_lo) out_lo[nt * 4] = __floats2half2_rn(c[nt].x * d_lo, c[nt].y * d_lo);
        if (ok_hi) out_hi[nt * 4] = __floats2half2_rn(c[nt].z * d_hi, c[nt].w * d_hi);
    }
}

// ---------------- pooling: batch is sorted -> run-length accumulate ----------------
// 256 threads: two half-block segments of 64 rows each; fp16 agg reads.
__global__ void __launch_bounds__(256) k_pool(const int* __restrict__ batch,
                       const float* __restrict__ gamma, const float* __restrict__ beta) {
    __shared__ int sb[128];
    int tid = threadIdx.x;
    int c = tid & 127;
    int seg = tid >> 7;              // 0 or 1
    int r0 = blockIdx.x * 128;
    int nrows = min(128, Nn - r0);
    if (tid < nrows) sb[tid] = batch[r0 + tid];
    float mean = g_bnsum[2 * Hh + c] * (1.0f / Nn);
    float var = g_bnsq[2 * Hh + c] * (1.0f / Nn) - mean * mean;
    float sc = gamma[c] * rsqrtf(var + EPSf);
    float sh = beta[c] - mean * sc;
    __syncthreads();
    int rbeg = seg * 64;
    int rend = min(nrows, rbeg + 64);
    if (rbeg >= rend) return;
    const __half* aggh = (const __half*)g_aggh;
    float acc = 0.f;
    int cur = sb[rbeg];
    for (int r = rbeg; r < rend; r++) {
        int gr = sb[r];
        if (gr != cur) { atomicAdd(&g_pooled[cur * Hh + c], acc); acc = 0.f; cur = gr; }
        float v = __half2float(aggh[(size_t)(r0 + r) * Hh + c]);
        acc += fmaxf(v * sc + sh, 0.f);
    }
    atomicAdd(&g_pooled[cur * Hh + c], acc);
}

// ---------------- final FC + TAIL ZEROING for next replay ----------------
__global__ void k_fc(const float* __restrict__ fcW, const float* __restrict__ fcb,
                     float* __restrict__ out) {
    int g = blockIdx.x, c = threadIdx.x;
    int t = g * 128 + c;
    float v = g_pooled[g * Hh + c] / fmaxf(g_cnt[g], 1.0f);
    g_pooled[g * Hh + c] = 0.0f;
    __shared__ float s0[128], s1[128], s2[128];
    s0[c] = v * fcW[c * 3 + 0];
    s1[c] = v * fcW[c * 3 + 1];
    s2[c] = v * fcW[c * 3 + 2];
    __syncthreads();
    for (int off = 64; off > 0; off >>= 1) {
        if (c < off) { s0[c] += s0[c + off]; s1[c] += s1[c + off]; s2[c] += s2[c + off]; }
        __syncthreads();
    }
    if (c == 0) {
        out[g * 3 + 0] = s0[0] + fcb[0];
        out[g * 3 + 1] = s1[0] + fcb[1];
        out[g * 3 + 2] = s2[0] + fcb[2];
        g_cnt[g] = 0.0f;
    }
    if (t < Nn) { g_degcnt[t] = 0; g_cursor[t] = 0; }
    if (t < SCAN_BLKS) g_sflag[t] = 0;
    if (t < 3 * Hh) { g_bnsum[t] = 0.0f; g_bnsq[t] = 0.0f; }
}

// ---------------- launch ----------------
extern "C" void kernel_launch(void* const* d_in, const int* in_sizes, int n_in,
                              void* d_out, int out_size) {
    const float* x     = (const float*)d_in[0];
    const int*   ei    = (const int*)  d_in[1];
    const int*   batch = (const int*)  d_in[2];
    const float* emb0  = (const float*)d_in[3];
    const float* emb1  = (const float*)d_in[4];
    const float* emb2  = (const float*)d_in[5];
    const float* emb5  = (const float*)d_in[6];
    const float* W1    = (const float*)d_in[7];
    const float* b1    = (const float*)d_in[8];
    const float* W2    = (const float*)d_in[9];
    const float* b2    = (const float*)d_in[10];
    const float* W3    = (const float*)d_in[11];
    const float* b3    = (const float*)d_in[12];
    const float* g1    = (const float*)d_in[13];
    const float* be1   = (const float*)d_in[14];
    const float* g2    = (const float*)d_in[15];
    const float* be2   = (const float*)d_in[16];
    const float* g3    = (const float*)d_in[17];
    const float* be3   = (const float*)d_in[18];
    const float* fcW   = (const float*)d_in[19];
    const float* fcb   = (const float*)d_in[20];
    float* out = (float*)d_out;

    cudaFuncSetAttribute(k_gemm, cudaFuncAttributeMaxDynamicSharedMemorySize, GEMM_SMEM);

    const int nblk = (Nn + 127) / 128;          // 391

    // 10-kernel critical path
    k_count<<<E4BLK, 256>>>(ei, batch);
    k_scan_proj<<<SCAN_BLKS + PROJ_BLKS, 256>>>(emb0, emb1, emb2, emb5, W1);
    k_place_layer1<<<E4BLK + L1BLK, 256>>>(ei, x, W1);

    k_gather<<<GBLK, 256>>>(0, b1);
    k_gemm<<<nblk, 256, GEMM_SMEM>>>(0, g1, be1, W2);
    k_gather<<<GBLK, 256>>>(1, b2);
    k_gemm<<<nblk, 256, GEMM_SMEM>>>(1, g2, be2, W3);
    k_gather<<<GBLK, 256>>>(2, b3);

    k_pool<<<nblk, 256>>>(batch, g3, be3);
    k_fc<<<Gg, 128>>>(fcW, fcb, out);
}